// round 14
// baseline (speedup 1.0000x reference)
#include <cuda_runtime.h>
#include <cuda_fp16.h>
#include <math.h>

#define N_NODES 100000
#define N_EDGES 1600000
#define N_GRAPHS 64
#define SLOPE 0.2f

// ---------------- scratch (device globals: allocation-free) ----------------
__device__ __half g_h1h[(size_t)N_NODES * 64];    // layer-1 output, fp16
__device__ __half g_Ah[(size_t)N_NODES * 256];    // layer-2 aggregated per-head features, fp16
__device__ float  g_es[N_NODES * 4];
__device__ float  g_ed[N_NODES * 4];
__device__ float  g_es2[N_NODES * 4];
__device__ float  g_ed2[N_NODES * 4];
__device__ int    g_colsrc[N_EDGES];
__device__ int    g_cnt[N_NODES];
__device__ int    g_fill[N_NODES];
__device__ int    g_tmp[N_NODES];
__device__ int    g_rowptr[N_NODES + 1];
__device__ int    g_bsum[128];
__device__ int    g_boff[128];
__device__ int    g_scan_done;
__device__ float  g_P1[24];
__device__ float  g_P2[512];
__device__ __half g_W2f[64 * 256];   // [c][kk] = 0.25 * W2[k, h*64+c]

// ---------------- prep ----------------
__global__ void k_zero(float* __restrict__ out) {
    int i = blockIdx.x * blockDim.x + threadIdx.x;
    if (i < N_NODES) { g_cnt[i] = 0; g_fill[i] = 0; }
    if (i < N_GRAPHS * 64) out[i] = 0.f;
    if (i == 0) g_scan_done = 0;
}

__global__ void k_count(const int* __restrict__ ei) {
    int i = blockIdx.x * blockDim.x + threadIdx.x;
    if (i < N_EDGES) atomicAdd(&g_cnt[ei[N_EDGES + i]], 1);
}

// grid 33 x 512: block 0 -> P1 + P2 ; blocks 1..32 -> W2f copy (parallel)
__global__ void k_prep(const float* __restrict__ W1, const float* __restrict__ as1,
                       const float* __restrict__ ad1, const float* __restrict__ W2,
                       const float* __restrict__ as2, const float* __restrict__ ad2) {
    int t = threadIdx.x;
    if (blockIdx.x == 0) {
        {
            int k = t >> 3, r = t & 7, h = r >> 1;
            const float* a = (r & 1) ? ad2 : as2;
            float s = 0.f;
            #pragma unroll 8
            for (int c = 0; c < 64; c++) s += W2[k * 256 + h * 64 + c] * a[h * 64 + c];
            g_P2[t] = s;
        }
        if (t < 24) {
            int k = t >> 3, r = t & 7, h = r >> 1;
            const float* a = (r & 1) ? ad1 : as1;
            float s = 0.f;
            #pragma unroll 8
            for (int c = 0; c < 64; c++) s += W1[k * 256 + h * 64 + c] * a[h * 64 + c];
            g_P1[t] = s;
        }
    } else {
        int idx = (blockIdx.x - 1) * 512 + t;
        int c = idx >> 8, kk = idx & 255;
        int h = kk >> 6, k = kk & 63;
        g_W2f[idx] = __float2half(0.25f * W2[k * 256 + h * 64 + c]);
    }
}

// ---------------- scan: shuffle scan + PARALLEL last-block tail ----------------
__global__ void k_scan1() {
    __shared__ int wsum[32];
    __shared__ int amLast;
    int t = threadIdx.x;
    int idx = blockIdx.x * 1024 + t;
    int lane = t & 31, w = t >> 5;
    int v = (idx < N_NODES) ? g_cnt[idx] : 0;
    int s = v;
    #pragma unroll
    for (int o = 1; o < 32; o <<= 1) {
        int y = __shfl_up_sync(0xffffffffu, s, o);
        if (lane >= o) s += y;
    }
    if (lane == 31) wsum[w] = s;
    __syncthreads();
    if (w == 0) {
        int ws = wsum[lane];
        #pragma unroll
        for (int o = 1; o < 32; o <<= 1) {
            int y = __shfl_up_sync(0xffffffffu, ws, o);
            if (lane >= o) ws += y;
        }
        wsum[lane] = ws;
    }
    __syncthreads();
    int off = (w > 0) ? wsum[w - 1] : 0;
    if (idx < N_NODES) g_tmp[idx] = s + off;   // inclusive scan within block
    if (t == 1023) {
        g_bsum[blockIdx.x] = wsum[31];
        __threadfence();
        int done = atomicAdd(&g_scan_done, 1);
        amLast = (done == (int)gridDim.x - 1);
    }
    __syncthreads();
    if (amLast) {
        // parallel exclusive scan of g_bsum[0..gridDim.x) (gridDim.x <= 128)
        int vb = (t < (int)gridDim.x) ? g_bsum[t] : 0;
        int sc = vb;
        #pragma unroll
        for (int o = 1; o < 32; o <<= 1) {
            int y = __shfl_up_sync(0xffffffffu, sc, o);
            if (lane >= o) sc += y;
        }
        __syncthreads();                  // wsum reads above are done
        if (lane == 31) wsum[w] = sc;
        __syncthreads();
        if (w == 0) {
            int ws = wsum[lane];
            #pragma unroll
            for (int o = 1; o < 32; o <<= 1) {
                int y = __shfl_up_sync(0xffffffffu, ws, o);
                if (lane >= o) ws += y;
            }
            wsum[lane] = ws;
        }
        __syncthreads();
        int off2 = (w > 0) ? wsum[w - 1] : 0;
        if (t < (int)gridDim.x) g_boff[t] = sc + off2 - vb;   // exclusive
        if (t == 0) g_rowptr[N_NODES] = N_EDGES;
    }
}

// scan3 fused with layer-1 logits (es1/ed1 = x @ P1)
__global__ void k_scan3x(const float* __restrict__ x) {
    int i = blockIdx.x * blockDim.x + threadIdx.x;
    if (i >= N_NODES) return;
    g_rowptr[i] = g_tmp[i] - g_cnt[i] + g_boff[i >> 10];
    float x0 = x[i * 3 + 0], x1 = x[i * 3 + 1], x2 = x[i * 3 + 2];
    #pragma unroll
    for (int r = 0; r < 8; r++) {
        float v = x0 * g_P1[r] + x1 * g_P1[8 + r] + x2 * g_P1[16 + r];
        int h = r >> 1;
        if (r & 1) g_ed[i * 4 + h] = v;
        else       g_es[i * 4 + h] = v;
    }
}

__global__ void k_fill(const int* __restrict__ ei) {
    int i = blockIdx.x * blockDim.x + threadIdx.x;
    if (i < N_EDGES) {
        int s = ei[i];
        int d = ei[N_EDGES + i];
        int pos = g_rowptr[d] + atomicAdd(&g_fill[d], 1);
        g_colsrc[pos] = s;
    }
}

// ---------------- pack helpers ----------------
__device__ __forceinline__ unsigned pack_h2(float a, float b) {
    __half2 h = __floats2half2_rn(a, b);
    return *(unsigned*)&h;
}
__device__ __forceinline__ float2 unpack_h2(unsigned u) {
    return __half22float2(*(__half2*)&u);
}
__device__ __forceinline__ float lky(float v) {
    v = v > 0.f ? v : SLOPE * v;
    return fminf(fmaxf(v, -60.f), 60.f);
}

// ---------------- layer 1, fully fused (warp per node), 4-edge unroll [R12] ----------------
__global__ void __launch_bounds__(256) k_l1(const float* __restrict__ x,
                                            const float* __restrict__ W1,
                                            const float* __restrict__ b1) {
    __shared__ float w1s[768];
    __shared__ float p2s[512];
    __shared__ float sAn[8][13];
    for (int i = threadIdx.x; i < 768; i += 256) w1s[i] = W1[i];
    for (int i = threadIdx.x; i < 512; i += 256) p2s[i] = g_P2[i];
    __syncthreads();
    int warp = (blockIdx.x * blockDim.x + threadIdx.x) >> 5;
    if (warp >= N_NODES) return;
    int lane = threadIdx.x & 31;
    int wid = threadIdx.x >> 5;
    int n = warp;
    int h = lane >> 3, kp = lane & 7;
    float my_ed = g_ed[n * 4 + h];
    int beg = g_rowptr[n], end = g_rowptr[n + 1];

    float acc = 0.f, ssum = 0.f;
    int e = beg;
    for (; e + 4 <= end; e += 4) {
        int t0 = g_colsrc[e + 0];
        int t1 = g_colsrc[e + 1];
        int t2 = g_colsrc[e + 2];
        int t3 = g_colsrc[e + 3];
        float l0 = g_es[t0 * 4 + h];
        float l1 = g_es[t1 * 4 + h];
        float l2 = g_es[t2 * 4 + h];
        float l3 = g_es[t3 * 4 + h];
        float xa = (kp < 3) ? x[t0 * 3 + kp] : 0.f;
        float xb = (kp < 3) ? x[t1 * 3 + kp] : 0.f;
        float xc = (kp < 3) ? x[t2 * 3 + kp] : 0.f;
        float xd = (kp < 3) ? x[t3 * 3 + kp] : 0.f;
        float w0 = __expf(lky(l0 + my_ed));
        float w1 = __expf(lky(l1 + my_ed));
        float w2 = __expf(lky(l2 + my_ed));
        float w3 = __expf(lky(l3 + my_ed));
        ssum += (w0 + w1) + (w2 + w3);
        acc += (w0 * xa + w1 * xb) + (w2 * xc + w3 * xd);
    }
    for (; e < end; e++) {
        int t0 = g_colsrc[e];
        float w0 = __expf(lky(g_es[t0 * 4 + h] + my_ed));
        float xa = (kp < 3) ? x[t0 * 3 + kp] : 0.f;
        ssum += w0;
        acc += w0 * xa;
    }
    float inv = (end > beg) ? 1.f / ssum : 0.f;
    if (kp < 3) sAn[wid][h * 3 + kp] = acc * inv;
    __syncwarp();

    int c0 = lane * 2;
    float r0 = b1[c0], r1 = b1[c0 + 1];
    #pragma unroll
    for (int hh = 0; hh < 4; hh++)
        #pragma unroll
        for (int k = 0; k < 3; k++) {
            float a = sAn[wid][hh * 3 + k];
            r0 += 0.25f * a * w1s[k * 256 + hh * 64 + c0];
            r1 += 0.25f * a * w1s[k * 256 + hh * 64 + c0 + 1];
        }
    r0 = fmaxf(r0, 0.f);
    r1 = fmaxf(r1, 0.f);
    *(unsigned*)(g_h1h + (size_t)n * 64 + c0) = pack_h2(r0, r1);

    float ar[8];
    #pragma unroll
    for (int r = 0; r < 8; r++) ar[r] = r0 * p2s[c0 * 8 + r] + r1 * p2s[(c0 + 1) * 8 + r];
    #pragma unroll
    for (int o = 16; o; o >>= 1)
        #pragma unroll
        for (int r = 0; r < 8; r++) ar[r] += __shfl_xor_sync(0xffffffffu, ar[r], o);
    float v = ar[0];
    #pragma unroll
    for (int r = 1; r < 8; r++) if (lane == r) v = ar[r];
    if (lane < 8) {
        int hh = lane >> 1;
        if (lane & 1) g_ed2[n * 4 + hh] = v;
        else          g_es2[n * 4 + hh] = v;
    }
}

// ---------------- layer-2 aggregation (warp per node), 4-edge unroll [R12] ----------------
__global__ void __launch_bounds__(256) k_agg2() {
    int warp = (blockIdx.x * blockDim.x + threadIdx.x) >> 5;
    if (warp >= N_NODES) return;
    int lane = threadIdx.x & 31;
    int n = warp;
    int h = lane >> 3, kp = lane & 7;
    float my_ed = g_ed2[n * 4 + h];
    int beg = g_rowptr[n], end = g_rowptr[n + 1];

    const uint4* h14 = (const uint4*)g_h1h;   // node row = 8 uint4 (128 B)
    float acc[8] = {0, 0, 0, 0, 0, 0, 0, 0};
    float ssum = 0.f;
    int e = beg;
    for (; e + 4 <= end; e += 4) {
        int t0 = g_colsrc[e + 0];
        int t1 = g_colsrc[e + 1];
        int t2 = g_colsrc[e + 2];
        int t3 = g_colsrc[e + 3];
        float l0 = g_es2[t0 * 4 + h];
        float l1 = g_es2[t1 * 4 + h];
        float l2 = g_es2[t2 * 4 + h];
        float l3 = g_es2[t3 * 4 + h];
        uint4 r0 = h14[(size_t)t0 * 8 + kp];
        uint4 r1 = h14[(size_t)t1 * 8 + kp];
        uint4 r2 = h14[(size_t)t2 * 8 + kp];
        uint4 r3 = h14[(size_t)t3 * 8 + kp];
        float w0 = __expf(lky(l0 + my_ed));
        float w1 = __expf(lky(l1 + my_ed));
        float w2 = __expf(lky(l2 + my_ed));
        float w3 = __expf(lky(l3 + my_ed));
        ssum += (w0 + w1) + (w2 + w3);
        float2 f;
        f = unpack_h2(r0.x); acc[0] += w0 * f.x; acc[1] += w0 * f.y;
        f = unpack_h2(r0.y); acc[2] += w0 * f.x; acc[3] += w0 * f.y;
        f = unpack_h2(r0.z); acc[4] += w0 * f.x; acc[5] += w0 * f.y;
        f = unpack_h2(r0.w); acc[6] += w0 * f.x; acc[7] += w0 * f.y;
        f = unpack_h2(r1.x); acc[0] += w1 * f.x; acc[1] += w1 * f.y;
        f = unpack_h2(r1.y); acc[2] += w1 * f.x; acc[3] += w1 * f.y;
        f = unpack_h2(r1.z); acc[4] += w1 * f.x; acc[5] += w1 * f.y;
        f = unpack_h2(r1.w); acc[6] += w1 * f.x; acc[7] += w1 * f.y;
        f = unpack_h2(r2.x); acc[0] += w2 * f.x; acc[1] += w2 * f.y;
        f = unpack_h2(r2.y); acc[2] += w2 * f.x; acc[3] += w2 * f.y;
        f = unpack_h2(r2.z); acc[4] += w2 * f.x; acc[5] += w2 * f.y;
        f = unpack_h2(r2.w); acc[6] += w2 * f.x; acc[7] += w2 * f.y;
        f = unpack_h2(r3.x); acc[0] += w3 * f.x; acc[1] += w3 * f.y;
        f = unpack_h2(r3.y); acc[2] += w3 * f.x; acc[3] += w3 * f.y;
        f = unpack_h2(r3.z); acc[4] += w3 * f.x; acc[5] += w3 * f.y;
        f = unpack_h2(r3.w); acc[6] += w3 * f.x; acc[7] += w3 * f.y;
    }
    for (; e < end; e++) {
        int t0 = g_colsrc[e];
        float w0 = __expf(lky(g_es2[t0 * 4 + h] + my_ed));
        uint4 r0 = h14[(size_t)t0 * 8 + kp];
        ssum += w0;
        float2 f;
        f = unpack_h2(r0.x); acc[0] += w0 * f.x; acc[1] += w0 * f.y;
        f = unpack_h2(r0.y); acc[2] += w0 * f.x; acc[3] += w0 * f.y;
        f = unpack_h2(r0.z); acc[4] += w0 * f.x; acc[5] += w0 * f.y;
        f = unpack_h2(r0.w); acc[6] += w0 * f.x; acc[7] += w0 * f.y;
    }
    float inv = (end > beg) ? 1.f / ssum : 0.f;
    uint4 o;
    o.x = pack_h2(acc[0] * inv, acc[1] * inv);
    o.y = pack_h2(acc[2] * inv, acc[3] * inv);
    o.z = pack_h2(acc[4] * inv, acc[5] * inv);
    o.w = pack_h2(acc[6] * inv, acc[7] * inv);
    *(uint4*)(g_Ah + (size_t)n * 256 + lane * 8) = o;
}

// ---------------- output GEMM via HMMA + FUSED global-add-pool ----------------
__global__ void __launch_bounds__(256) k_out(const float* __restrict__ b2,
                                             const int* __restrict__ batch,
                                             float* __restrict__ out) {
    __shared__ __align__(16) char sbuf[32768];       // sA/sB aliased with sH
    __half* sA = (__half*)sbuf;                      // 128*72*2 = 18432 B
    __half* sB = (__half*)(sbuf + 18432);            // 64*72*2  =  9216 B
    float*  sH = (float*)sbuf;                       // 128*64*4 = 32768 B (reused)

    int n0 = blockIdx.x * 128;
    int tid = threadIdx.x, wid = tid >> 5, lane = tid & 31;
    int g = lane >> 2, tg = lane & 3;
    float acc[8][4];
    #pragma unroll
    for (int i = 0; i < 8; i++)
        #pragma unroll
        for (int j = 0; j < 4; j++) acc[i][j] = 0.f;

    for (int kc = 0; kc < 4; kc++) {
        int k0 = kc * 64;
        __syncthreads();
        #pragma unroll
        for (int i = 0; i < 4; i++) {
            int q = tid + i * 256;
            int r = q >> 3, u = q & 7;
            int node = n0 + r;
            uint4 v = make_uint4(0, 0, 0, 0);
            if (node < N_NODES) v = *(const uint4*)(g_Ah + (size_t)node * 256 + k0 + u * 8);
            *(uint4*)(sA + r * 72 + u * 8) = v;
        }
        #pragma unroll
        for (int i = 0; i < 2; i++) {
            int q = tid + i * 256;
            int c = q >> 3, u = q & 7;
            *(uint4*)(sB + c * 72 + u * 8) = *(const uint4*)(g_W2f + c * 256 + k0 + u * 8);
        }
        __syncthreads();
        #pragma unroll
        for (int ks = 0; ks < 4; ks++) {
            int k1 = ks * 16;
            int arow = wid * 16 + g;
            unsigned a0 = *(unsigned*)(sA + arow * 72 + k1 + tg * 2);
            unsigned a1 = *(unsigned*)(sA + (arow + 8) * 72 + k1 + tg * 2);
            unsigned a2 = *(unsigned*)(sA + arow * 72 + k1 + 8 + tg * 2);
            unsigned a3 = *(unsigned*)(sA + (arow + 8) * 72 + k1 + 8 + tg * 2);
            #pragma unroll
            for (int nt = 0; nt < 8; nt++) {
                unsigned b0 = *(unsigned*)(sB + (nt * 8 + g) * 72 + k1 + tg * 2);
                unsigned b1 = *(unsigned*)(sB + (nt * 8 + g) * 72 + k1 + 8 + tg * 2);
                asm volatile(
                    "mma.sync.aligned.m16n8k16.row.col.f32.f16.f16.f32 "
                    "{%0,%1,%2,%3}, {%4,%5,%6,%7}, {%8,%9}, {%0,%1,%2,%3};\n"
                    : "+f"(acc[nt][0]), "+f"(acc[nt][1]), "+f"(acc[nt][2]), "+f"(acc[nt][3])
                    : "r"(a0), "r"(a1), "r"(a2), "r"(a3), "r"(b0), "r"(b1));
            }
        }
    }
    __syncthreads();   // done with sA/sB; sH takes over the buffer

    int row0 = wid * 16 + g;   // local row within tile
    #pragma unroll
    for (int nt = 0; nt < 8; nt++) {
        int c = nt * 8 + tg * 2;
        float bb0 = b2[c], bb1 = b2[c + 1];
        sH[row0 * 64 + c]       = fmaxf(acc[nt][0] + bb0, 0.f);
        sH[row0 * 64 + c + 1]   = fmaxf(acc[nt][1] + bb1, 0.f);
        sH[(row0 + 8) * 64 + c]     = fmaxf(acc[nt][2] + bb0, 0.f);
        sH[(row0 + 8) * 64 + c + 1] = fmaxf(acc[nt][3] + bb1, 0.f);
    }
    __syncthreads();

    // pooled reduction: 4 threads per channel, each scans 32 rows
    int c = tid & 63;
    int part = tid >> 6;           // 0..3
    int r0 = part * 32;
    float pacc = 0.f;
    int cur = -1;
    #pragma unroll 4
    for (int r = r0; r < r0 + 32; r++) {
        int node = n0 + r;
        if (node >= N_NODES) break;
        int gg = batch[node];
        if (gg != cur) {
            if (cur >= 0) atomicAdd(&out[cur * 64 + c], pacc);
            cur = gg;
            pacc = 0.f;
        }
        pacc += sH[r * 64 + c];
    }
    if (cur >= 0) atomicAdd(&out[cur * 64 + c], pacc);
}

// ---------------- launch ----------------
extern "C" void kernel_launch(void* const* d_in, const int* in_sizes, int n_in,
                              void* d_out, int out_size) {
    const float* x     = (const float*)d_in[0];
    const int*   ei    = (const int*)d_in[1];
    const int*   batch = (const int*)d_in[2];
    const float* W1 = (const float*)d_in[3];
    const float* a_src1 = (const float*)d_in[4];
    const float* a_dst1 = (const float*)d_in[5];
    const float* b1 = (const float*)d_in[6];
    const float* W2 = (const float*)d_in[7];
    const float* a_src2 = (const float*)d_in[8];
    const float* a_dst2 = (const float*)d_in[9];
    const float* b2 = (const float*)d_in[10];
    float* out = (float*)d_out;

    const int NB_N  = (N_NODES + 255) / 256;
    const int NB_E  = (N_EDGES + 255) / 256;
    const int NB_W  = (N_NODES * 32 + 255) / 256;
    const int NB_S1 = (N_NODES + 1023) / 1024;
    const int NB_O  = (N_NODES + 127) / 128;

    k_zero<<<NB_N, 256>>>(out);
    k_count<<<NB_E, 256>>>(ei);
    k_prep<<<33, 512>>>(W1, a_src1, a_dst1, W2, a_src2, a_dst2);
    k_scan1<<<NB_S1, 1024>>>();                    // idx 3: ncu verifies tail fix
    k_scan3x<<<NB_N, 256>>>(x);
    k_fill<<<NB_E, 256>>>(ei);

    // DIAGNOSTIC duplicates: k_l1 and k_agg2 are idempotent, so running each
    // twice is correctness-neutral; the dur delta measures their true cost.
    k_l1<<<NB_W, 256>>>(x, W1, b1);
    k_l1<<<NB_W, 256>>>(x, W1, b1);
    k_agg2<<<NB_W, 256>>>();
    k_agg2<<<NB_W, 256>>>();
    k_out<<<NB_O, 256>>>(b2, batch, out);
}

// round 15
// speedup vs baseline: 1.0995x; 1.0995x over previous
#include <cuda_runtime.h>
#include <cuda_fp16.h>
#include <math.h>

#define N_NODES 100000
#define N_EDGES 1600000
#define N_GRAPHS 64
#define SLOPE 0.2f

// ---------------- scratch (device globals: allocation-free) ----------------
__device__ __half g_h1h[(size_t)N_NODES * 64];    // layer-1 output, fp16
__device__ __half g_Ah[(size_t)N_NODES * 256];    // layer-2 aggregated per-head features, fp16
__device__ float  g_es[N_NODES * 4];
__device__ float  g_ed[N_NODES * 4];
__device__ float  g_es2[N_NODES * 4];
__device__ float  g_ed2[N_NODES * 4];
__device__ int    g_colsrc[N_EDGES];
__device__ int    g_cnt[N_NODES];
__device__ int    g_fill[N_NODES];
__device__ int    g_tmp[N_NODES];
__device__ int    g_rowptr[N_NODES + 1];
__device__ int    g_bsum[128];
__device__ int    g_boff[128];
__device__ int    g_scan_done;
__device__ float  g_P1[24];
__device__ float  g_P2[512];
__device__ __half g_W2f[64 * 256];   // [c][kk] = 0.25 * W2[k, h*64+c]

// ---------------- prep ----------------
__global__ void k_zero(float* __restrict__ out) {
    int i = blockIdx.x * blockDim.x + threadIdx.x;
    if (i < N_NODES) { g_cnt[i] = 0; g_fill[i] = 0; }
    if (i < N_GRAPHS * 64) out[i] = 0.f;
    if (i == 0) g_scan_done = 0;
}

__global__ void k_count(const int* __restrict__ ei) {
    int i = blockIdx.x * blockDim.x + threadIdx.x;
    if (i < N_EDGES) atomicAdd(&g_cnt[ei[N_EDGES + i]], 1);
}

// grid 33 x 512: block 0 -> P1 + P2 ; blocks 1..32 -> W2f copy (parallel)
__global__ void k_prep(const float* __restrict__ W1, const float* __restrict__ as1,
                       const float* __restrict__ ad1, const float* __restrict__ W2,
                       const float* __restrict__ as2, const float* __restrict__ ad2) {
    int t = threadIdx.x;
    if (blockIdx.x == 0) {
        {
            int k = t >> 3, r = t & 7, h = r >> 1;
            const float* a = (r & 1) ? ad2 : as2;
            float s = 0.f;
            #pragma unroll 8
            for (int c = 0; c < 64; c++) s += W2[k * 256 + h * 64 + c] * a[h * 64 + c];
            g_P2[t] = s;
        }
        if (t < 24) {
            int k = t >> 3, r = t & 7, h = r >> 1;
            const float* a = (r & 1) ? ad1 : as1;
            float s = 0.f;
            #pragma unroll 8
            for (int c = 0; c < 64; c++) s += W1[k * 256 + h * 64 + c] * a[h * 64 + c];
            g_P1[t] = s;
        }
    } else {
        int idx = (blockIdx.x - 1) * 512 + t;
        int c = idx >> 8, kk = idx & 255;
        int h = kk >> 6, k = kk & 63;
        g_W2f[idx] = __float2half(0.25f * W2[k * 256 + h * 64 + c]);
    }
}

// ---------------- scan: shuffle scan + parallel last-block tail ----------------
__global__ void k_scan1() {
    __shared__ int wsum[32];
    __shared__ int amLast;
    int t = threadIdx.x;
    int idx = blockIdx.x * 1024 + t;
    int lane = t & 31, w = t >> 5;
    int v = (idx < N_NODES) ? g_cnt[idx] : 0;
    int s = v;
    #pragma unroll
    for (int o = 1; o < 32; o <<= 1) {
        int y = __shfl_up_sync(0xffffffffu, s, o);
        if (lane >= o) s += y;
    }
    if (lane == 31) wsum[w] = s;
    __syncthreads();
    if (w == 0) {
        int ws = wsum[lane];
        #pragma unroll
        for (int o = 1; o < 32; o <<= 1) {
            int y = __shfl_up_sync(0xffffffffu, ws, o);
            if (lane >= o) ws += y;
        }
        wsum[lane] = ws;
    }
    __syncthreads();
    int off = (w > 0) ? wsum[w - 1] : 0;
    if (idx < N_NODES) g_tmp[idx] = s + off;
    if (t == 1023) {
        g_bsum[blockIdx.x] = wsum[31];
        __threadfence();
        int done = atomicAdd(&g_scan_done, 1);
        amLast = (done == (int)gridDim.x - 1);
    }
    __syncthreads();
    if (amLast) {
        int vb = (t < (int)gridDim.x) ? g_bsum[t] : 0;
        int sc = vb;
        #pragma unroll
        for (int o = 1; o < 32; o <<= 1) {
            int y = __shfl_up_sync(0xffffffffu, sc, o);
            if (lane >= o) sc += y;
        }
        __syncthreads();
        if (lane == 31) wsum[w] = sc;
        __syncthreads();
        if (w == 0) {
            int ws = wsum[lane];
            #pragma unroll
            for (int o = 1; o < 32; o <<= 1) {
                int y = __shfl_up_sync(0xffffffffu, ws, o);
                if (lane >= o) ws += y;
            }
            wsum[lane] = ws;
        }
        __syncthreads();
        int off2 = (w > 0) ? wsum[w - 1] : 0;
        if (t < (int)gridDim.x) g_boff[t] = sc + off2 - vb;
        if (t == 0) g_rowptr[N_NODES] = N_EDGES;
    }
}

// scan3 fused with layer-1 logits (es1/ed1 = x @ P1)
__global__ void k_scan3x(const float* __restrict__ x) {
    int i = blockIdx.x * blockDim.x + threadIdx.x;
    if (i >= N_NODES) return;
    g_rowptr[i] = g_tmp[i] - g_cnt[i] + g_boff[i >> 10];
    float x0 = x[i * 3 + 0], x1 = x[i * 3 + 1], x2 = x[i * 3 + 2];
    #pragma unroll
    for (int r = 0; r < 8; r++) {
        float v = x0 * g_P1[r] + x1 * g_P1[8 + r] + x2 * g_P1[16 + r];
        int h = r >> 1;
        if (r & 1) g_ed[i * 4 + h] = v;
        else       g_es[i * 4 + h] = v;
    }
}

__global__ void k_fill(const int* __restrict__ ei) {
    int i = blockIdx.x * blockDim.x + threadIdx.x;
    if (i < N_EDGES) {
        int s = ei[i];
        int d = ei[N_EDGES + i];
        int pos = g_rowptr[d] + atomicAdd(&g_fill[d], 1);
        g_colsrc[pos] = s;
    }
}

// ---------------- pack helpers ----------------
__device__ __forceinline__ unsigned pack_h2(float a, float b) {
    __half2 h = __floats2half2_rn(a, b);
    return *(unsigned*)&h;
}
__device__ __forceinline__ float2 unpack_h2(unsigned u) {
    return __half22float2(*(__half2*)&u);
}
__device__ __forceinline__ float lky(float v) {
    v = v > 0.f ? v : SLOPE * v;
    return fminf(fmaxf(v, -60.f), 60.f);
}

// ---------------- layer 1, fused; (edge-slot x head) lane layout ----------------
// lane = eg*4 + h (eg = 0..7 edge slot, h = 0..3 head): 8 edges/iter,
// exactly 1 expf + 3 FFMA per lane per iteration (no lane redundancy).
__global__ void __launch_bounds__(256) k_l1(const float* __restrict__ x,
                                            const float* __restrict__ W1,
                                            const float* __restrict__ b1) {
    __shared__ float w1s[768];
    __shared__ float p2s[512];
    __shared__ float sAn[8][13];
    for (int i = threadIdx.x; i < 768; i += 256) w1s[i] = W1[i];
    for (int i = threadIdx.x; i < 512; i += 256) p2s[i] = g_P2[i];
    __syncthreads();
    int warp = (blockIdx.x * blockDim.x + threadIdx.x) >> 5;
    if (warp >= N_NODES) return;
    int lane = threadIdx.x & 31;
    int wid = threadIdx.x >> 5;
    int n = warp;
    int h = lane & 3;           // head
    int eg = lane >> 2;         // edge slot 0..7
    float my_ed = g_ed[n * 4 + h];
    int beg = g_rowptr[n], end = g_rowptr[n + 1];

    float a0 = 0.f, a1 = 0.f, a2 = 0.f, ss = 0.f;
    for (int base = beg; base < end; base += 8) {
        int idx = base + eg;
        bool valid = idx < end;
        int t = valid ? g_colsrc[idx] : 0;
        float l = g_es[t * 4 + h];
        float w = valid ? __expf(lky(l + my_ed)) : 0.f;
        float x0 = x[t * 3 + 0];
        float x1 = x[t * 3 + 1];
        float x2 = x[t * 3 + 2];
        ss += w;
        a0 += w * x0;
        a1 += w * x1;
        a2 += w * x2;
    }
    // reduce over the 8 edge slots (lane bits 2..4)
    #pragma unroll
    for (int o = 4; o <= 16; o <<= 1) {
        ss += __shfl_xor_sync(0xffffffffu, ss, o);
        a0 += __shfl_xor_sync(0xffffffffu, a0, o);
        a1 += __shfl_xor_sync(0xffffffffu, a1, o);
        a2 += __shfl_xor_sync(0xffffffffu, a2, o);
    }
    float inv = (end > beg) ? 1.f / ss : 0.f;
    if (lane < 4) {             // lanes 0..3 hold heads 0..3
        sAn[wid][h * 3 + 0] = a0 * inv;
        sAn[wid][h * 3 + 1] = a1 * inv;
        sAn[wid][h * 3 + 2] = a2 * inv;
    }
    __syncwarp();

    // h1 channels c0, c0+1 for this lane
    int c0 = lane * 2;
    float r0 = b1[c0], r1 = b1[c0 + 1];
    #pragma unroll
    for (int hh = 0; hh < 4; hh++)
        #pragma unroll
        for (int k = 0; k < 3; k++) {
            float a = sAn[wid][hh * 3 + k];
            r0 += 0.25f * a * w1s[k * 256 + hh * 64 + c0];
            r1 += 0.25f * a * w1s[k * 256 + hh * 64 + c0 + 1];
        }
    r0 = fmaxf(r0, 0.f);
    r1 = fmaxf(r1, 0.f);
    *(unsigned*)(g_h1h + (size_t)n * 64 + c0) = pack_h2(r0, r1);

    // layer-2 logits (es2/ed2 = h1 @ P2)
    float ar[8];
    #pragma unroll
    for (int r = 0; r < 8; r++) ar[r] = r0 * p2s[c0 * 8 + r] + r1 * p2s[(c0 + 1) * 8 + r];
    #pragma unroll
    for (int o = 16; o; o >>= 1)
        #pragma unroll
        for (int r = 0; r < 8; r++) ar[r] += __shfl_xor_sync(0xffffffffu, ar[r], o);
    float v = ar[0];
    #pragma unroll
    for (int r = 1; r < 8; r++) if (lane == r) v = ar[r];
    if (lane < 8) {
        int hh = lane >> 1;
        if (lane & 1) g_ed2[n * 4 + hh] = v;
        else          g_es2[n * 4 + hh] = v;
    }
}

// ---------------- layer-2 aggregation (warp per node), 4-edge unroll [R12] ----------------
__global__ void __launch_bounds__(256) k_agg2() {
    int warp = (blockIdx.x * blockDim.x + threadIdx.x) >> 5;
    if (warp >= N_NODES) return;
    int lane = threadIdx.x & 31;
    int n = warp;
    int h = lane >> 3, kp = lane & 7;
    float my_ed = g_ed2[n * 4 + h];
    int beg = g_rowptr[n], end = g_rowptr[n + 1];

    const uint4* h14 = (const uint4*)g_h1h;   // node row = 8 uint4 (128 B)
    float acc[8] = {0, 0, 0, 0, 0, 0, 0, 0};
    float ssum = 0.f;
    int e = beg;
    for (; e + 4 <= end; e += 4) {
        int t0 = g_colsrc[e + 0];
        int t1 = g_colsrc[e + 1];
        int t2 = g_colsrc[e + 2];
        int t3 = g_colsrc[e + 3];
        float l0 = g_es2[t0 * 4 + h];
        float l1 = g_es2[t1 * 4 + h];
        float l2 = g_es2[t2 * 4 + h];
        float l3 = g_es2[t3 * 4 + h];
        uint4 r0 = h14[(size_t)t0 * 8 + kp];
        uint4 r1 = h14[(size_t)t1 * 8 + kp];
        uint4 r2 = h14[(size_t)t2 * 8 + kp];
        uint4 r3 = h14[(size_t)t3 * 8 + kp];
        float w0 = __expf(lky(l0 + my_ed));
        float w1 = __expf(lky(l1 + my_ed));
        float w2 = __expf(lky(l2 + my_ed));
        float w3 = __expf(lky(l3 + my_ed));
        ssum += (w0 + w1) + (w2 + w3);
        float2 f;
        f = unpack_h2(r0.x); acc[0] += w0 * f.x; acc[1] += w0 * f.y;
        f = unpack_h2(r0.y); acc[2] += w0 * f.x; acc[3] += w0 * f.y;
        f = unpack_h2(r0.z); acc[4] += w0 * f.x; acc[5] += w0 * f.y;
        f = unpack_h2(r0.w); acc[6] += w0 * f.x; acc[7] += w0 * f.y;
        f = unpack_h2(r1.x); acc[0] += w1 * f.x; acc[1] += w1 * f.y;
        f = unpack_h2(r1.y); acc[2] += w1 * f.x; acc[3] += w1 * f.y;
        f = unpack_h2(r1.z); acc[4] += w1 * f.x; acc[5] += w1 * f.y;
        f = unpack_h2(r1.w); acc[6] += w1 * f.x; acc[7] += w1 * f.y;
        f = unpack_h2(r2.x); acc[0] += w2 * f.x; acc[1] += w2 * f.y;
        f = unpack_h2(r2.y); acc[2] += w2 * f.x; acc[3] += w2 * f.y;
        f = unpack_h2(r2.z); acc[4] += w2 * f.x; acc[5] += w2 * f.y;
        f = unpack_h2(r2.w); acc[6] += w2 * f.x; acc[7] += w2 * f.y;
        f = unpack_h2(r3.x); acc[0] += w3 * f.x; acc[1] += w3 * f.y;
        f = unpack_h2(r3.y); acc[2] += w3 * f.x; acc[3] += w3 * f.y;
        f = unpack_h2(r3.z); acc[4] += w3 * f.x; acc[5] += w3 * f.y;
        f = unpack_h2(r3.w); acc[6] += w3 * f.x; acc[7] += w3 * f.y;
    }
    for (; e < end; e++) {
        int t0 = g_colsrc[e];
        float w0 = __expf(lky(g_es2[t0 * 4 + h] + my_ed));
        uint4 r0 = h14[(size_t)t0 * 8 + kp];
        ssum += w0;
        float2 f;
        f = unpack_h2(r0.x); acc[0] += w0 * f.x; acc[1] += w0 * f.y;
        f = unpack_h2(r0.y); acc[2] += w0 * f.x; acc[3] += w0 * f.y;
        f = unpack_h2(r0.z); acc[4] += w0 * f.x; acc[5] += w0 * f.y;
        f = unpack_h2(r0.w); acc[6] += w0 * f.x; acc[7] += w0 * f.y;
    }
    float inv = (end > beg) ? 1.f / ssum : 0.f;
    uint4 o;
    o.x = pack_h2(acc[0] * inv, acc[1] * inv);
    o.y = pack_h2(acc[2] * inv, acc[3] * inv);
    o.z = pack_h2(acc[4] * inv, acc[5] * inv);
    o.w = pack_h2(acc[6] * inv, acc[7] * inv);
    *(uint4*)(g_Ah + (size_t)n * 256 + lane * 8) = o;
}

// ---------------- output GEMM via HMMA + FUSED global-add-pool ----------------
__global__ void __launch_bounds__(256) k_out(const float* __restrict__ b2,
                                             const int* __restrict__ batch,
                                             float* __restrict__ out) {
    __shared__ __align__(16) char sbuf[32768];       // sA/sB aliased with sH
    __half* sA = (__half*)sbuf;                      // 128*72*2 = 18432 B
    __half* sB = (__half*)(sbuf + 18432);            // 64*72*2  =  9216 B
    float*  sH = (float*)sbuf;                       // 128*64*4 = 32768 B (reused)

    int n0 = blockIdx.x * 128;
    int tid = threadIdx.x, wid = tid >> 5, lane = tid & 31;
    int g = lane >> 2, tg = lane & 3;
    float acc[8][4];
    #pragma unroll
    for (int i = 0; i < 8; i++)
        #pragma unroll
        for (int j = 0; j < 4; j++) acc[i][j] = 0.f;

    for (int kc = 0; kc < 4; kc++) {
        int k0 = kc * 64;
        __syncthreads();
        #pragma unroll
        for (int i = 0; i < 4; i++) {
            int q = tid + i * 256;
            int r = q >> 3, u = q & 7;
            int node = n0 + r;
            uint4 v = make_uint4(0, 0, 0, 0);
            if (node < N_NODES) v = *(const uint4*)(g_Ah + (size_t)node * 256 + k0 + u * 8);
            *(uint4*)(sA + r * 72 + u * 8) = v;
        }
        #pragma unroll
        for (int i = 0; i < 2; i++) {
            int q = tid + i * 256;
            int c = q >> 3, u = q & 7;
            *(uint4*)(sB + c * 72 + u * 8) = *(const uint4*)(g_W2f + c * 256 + k0 + u * 8);
        }
        __syncthreads();
        #pragma unroll
        for (int ks = 0; ks < 4; ks++) {
            int k1 = ks * 16;
            int arow = wid * 16 + g;
            unsigned a0 = *(unsigned*)(sA + arow * 72 + k1 + tg * 2);
            unsigned a1 = *(unsigned*)(sA + (arow + 8) * 72 + k1 + tg * 2);
            unsigned a2 = *(unsigned*)(sA + arow * 72 + k1 + 8 + tg * 2);
            unsigned a3 = *(unsigned*)(sA + (arow + 8) * 72 + k1 + 8 + tg * 2);
            #pragma unroll
            for (int nt = 0; nt < 8; nt++) {
                unsigned b0 = *(unsigned*)(sB + (nt * 8 + g) * 72 + k1 + tg * 2);
                unsigned b1 = *(unsigned*)(sB + (nt * 8 + g) * 72 + k1 + 8 + tg * 2);
                asm volatile(
                    "mma.sync.aligned.m16n8k16.row.col.f32.f16.f16.f32 "
                    "{%0,%1,%2,%3}, {%4,%5,%6,%7}, {%8,%9}, {%0,%1,%2,%3};\n"
                    : "+f"(acc[nt][0]), "+f"(acc[nt][1]), "+f"(acc[nt][2]), "+f"(acc[nt][3])
                    : "r"(a0), "r"(a1), "r"(a2), "r"(a3), "r"(b0), "r"(b1));
            }
        }
    }
    __syncthreads();   // done with sA/sB; sH takes over the buffer

    int row0 = wid * 16 + g;   // local row within tile
    #pragma unroll
    for (int nt = 0; nt < 8; nt++) {
        int c = nt * 8 + tg * 2;
        float bb0 = b2[c], bb1 = b2[c + 1];
        sH[row0 * 64 + c]       = fmaxf(acc[nt][0] + bb0, 0.f);
        sH[row0 * 64 + c + 1]   = fmaxf(acc[nt][1] + bb1, 0.f);
        sH[(row0 + 8) * 64 + c]     = fmaxf(acc[nt][2] + bb0, 0.f);
        sH[(row0 + 8) * 64 + c + 1] = fmaxf(acc[nt][3] + bb1, 0.f);
    }
    __syncthreads();

    // pooled reduction: 4 threads per channel, each scans 32 rows
    int c = tid & 63;
    int part = tid >> 6;
    int r0 = part * 32;
    float pacc = 0.f;
    int cur = -1;
    #pragma unroll 4
    for (int r = r0; r < r0 + 32; r++) {
        int node = n0 + r;
        if (node >= N_NODES) break;
        int gg = batch[node];
        if (gg != cur) {
            if (cur >= 0) atomicAdd(&out[cur * 64 + c], pacc);
            cur = gg;
            pacc = 0.f;
        }
        pacc += sH[r * 64 + c];
    }
    if (cur >= 0) atomicAdd(&out[cur * 64 + c], pacc);
}

// ---------------- launch ----------------
extern "C" void kernel_launch(void* const* d_in, const int* in_sizes, int n_in,
                              void* d_out, int out_size) {
    const float* x     = (const float*)d_in[0];
    const int*   ei    = (const int*)d_in[1];
    const int*   batch = (const int*)d_in[2];
    const float* W1 = (const float*)d_in[3];
    const float* a_src1 = (const float*)d_in[4];
    const float* a_dst1 = (const float*)d_in[5];
    const float* b1 = (const float*)d_in[6];
    const float* W2 = (const float*)d_in[7];
    const float* a_src2 = (const float*)d_in[8];
    const float* a_dst2 = (const float*)d_in[9];
    const float* b2 = (const float*)d_in[10];
    float* out = (float*)d_out;

    const int NB_N  = (N_NODES + 255) / 256;
    const int NB_E  = (N_EDGES + 255) / 256;
    const int NB_W  = (N_NODES * 32 + 255) / 256;
    const int NB_S1 = (N_NODES + 1023) / 1024;
    const int NB_O  = (N_NODES + 127) / 128;

    k_zero<<<NB_N, 256>>>(out);
    k_count<<<NB_E, 256>>>(ei);
    k_prep<<<33, 512>>>(W1, a_src1, a_dst1, W2, a_src2, a_dst2);
    k_scan1<<<NB_S1, 1024>>>();
    k_scan3x<<<NB_N, 256>>>(x);
    k_fill<<<NB_E, 256>>>(ei);

    k_l1<<<NB_W, 256>>>(x, W1, b1);
    k_agg2<<<NB_W, 256>>>();
    k_out<<<NB_O, 256>>>(b2, batch, out);
}

// round 16
// speedup vs baseline: 1.7601x; 1.6008x over previous
#include <cuda_runtime.h>
#include <cuda_fp16.h>
#include <math.h>

#define N_NODES 100000
#define N_EDGES 1600000
#define N_GRAPHS 64
#define SLOPE 0.2f

// ---------------- scratch (device globals: allocation-free) ----------------
__device__ __half g_h1h[(size_t)N_NODES * 64];    // layer-1 output, fp16
__device__ __half g_Ah[(size_t)N_NODES * 256];    // layer-2 aggregated per-head features, fp16
__device__ float  g_A1[(size_t)N_NODES * 12];     // layer-1 aggregated per-head raw features
__device__ float  g_es[N_NODES * 4];
__device__ float  g_ed[N_NODES * 4];
__device__ float  g_es2[N_NODES * 4];
__device__ float  g_ed2[N_NODES * 4];
__device__ int    g_colsrc[N_EDGES];
__device__ int    g_cnt[N_NODES];
__device__ int    g_fill[N_NODES];
__device__ int    g_tmp[N_NODES];
__device__ int    g_rowptr[N_NODES + 1];
__device__ int    g_bsum[128];
__device__ int    g_boff[128];
__device__ int    g_scan_done;
__device__ float  g_P1[24];
__device__ float  g_P2[512];
__device__ __half g_W2f[64 * 256];   // [c][kk] = 0.25 * W2[k, h*64+c]

// ---------------- prep ----------------
__global__ void k_zero(float* __restrict__ out) {
    int i = blockIdx.x * blockDim.x + threadIdx.x;
    if (i < N_NODES) { g_cnt[i] = 0; g_fill[i] = 0; }
    if (i < N_GRAPHS * 64) out[i] = 0.f;
    if (i == 0) g_scan_done = 0;
}

__global__ void k_count(const int* __restrict__ ei) {
    int i = blockIdx.x * blockDim.x + threadIdx.x;
    if (i < N_EDGES) atomicAdd(&g_cnt[ei[N_EDGES + i]], 1);
}

// grid 33 x 512: block 0 -> P1 + P2 ; blocks 1..32 -> W2f copy (parallel)
__global__ void k_prep(const float* __restrict__ W1, const float* __restrict__ as1,
                       const float* __restrict__ ad1, const float* __restrict__ W2,
                       const float* __restrict__ as2, const float* __restrict__ ad2) {
    int t = threadIdx.x;
    if (blockIdx.x == 0) {
        {
            int k = t >> 3, r = t & 7, h = r >> 1;
            const float* a = (r & 1) ? ad2 : as2;
            float s = 0.f;
            #pragma unroll 8
            for (int c = 0; c < 64; c++) s += W2[k * 256 + h * 64 + c] * a[h * 64 + c];
            g_P2[t] = s;
        }
        if (t < 24) {
            int k = t >> 3, r = t & 7, h = r >> 1;
            const float* a = (r & 1) ? ad1 : as1;
            float s = 0.f;
            #pragma unroll 8
            for (int c = 0; c < 64; c++) s += W1[k * 256 + h * 64 + c] * a[h * 64 + c];
            g_P1[t] = s;
        }
    } else {
        int idx = (blockIdx.x - 1) * 512 + t;
        int c = idx >> 8, kk = idx & 255;
        int h = kk >> 6, k = kk & 63;
        g_W2f[idx] = __float2half(0.25f * W2[k * 256 + h * 64 + c]);
    }
}

// ---------------- scan: shuffle scan + parallel last-block tail (verified R14) ----
__global__ void k_scan1() {
    __shared__ int wsum[32];
    __shared__ int amLast;
    int t = threadIdx.x;
    int idx = blockIdx.x * 1024 + t;
    int lane = t & 31, w = t >> 5;
    int v = (idx < N_NODES) ? g_cnt[idx] : 0;
    int s = v;
    #pragma unroll
    for (int o = 1; o < 32; o <<= 1) {
        int y = __shfl_up_sync(0xffffffffu, s, o);
        if (lane >= o) s += y;
    }
    if (lane == 31) wsum[w] = s;
    __syncthreads();
    if (w == 0) {
        int ws = wsum[lane];
        #pragma unroll
        for (int o = 1; o < 32; o <<= 1) {
            int y = __shfl_up_sync(0xffffffffu, ws, o);
            if (lane >= o) ws += y;
        }
        wsum[lane] = ws;
    }
    __syncthreads();
    int off = (w > 0) ? wsum[w - 1] : 0;
    if (idx < N_NODES) g_tmp[idx] = s + off;
    if (t == 1023) {
        g_bsum[blockIdx.x] = wsum[31];
        __threadfence();
        int done = atomicAdd(&g_scan_done, 1);
        amLast = (done == (int)gridDim.x - 1);
    }
    __syncthreads();
    if (amLast) {
        int vb = (t < (int)gridDim.x) ? g_bsum[t] : 0;
        int sc = vb;
        #pragma unroll
        for (int o = 1; o < 32; o <<= 1) {
            int y = __shfl_up_sync(0xffffffffu, sc, o);
            if (lane >= o) sc += y;
        }
        __syncthreads();
        if (lane == 31) wsum[w] = sc;
        __syncthreads();
        if (w == 0) {
            int ws = wsum[lane];
            #pragma unroll
            for (int o = 1; o < 32; o <<= 1) {
                int y = __shfl_up_sync(0xffffffffu, ws, o);
                if (lane >= o) ws += y;
            }
            wsum[lane] = ws;
        }
        __syncthreads();
        int off2 = (w > 0) ? wsum[w - 1] : 0;
        if (t < (int)gridDim.x) g_boff[t] = sc + off2 - vb;
        if (t == 0) g_rowptr[N_NODES] = N_EDGES;
    }
}

// scan3 fused with layer-1 logits (es1/ed1 = x @ P1)
__global__ void k_scan3x(const float* __restrict__ x) {
    int i = blockIdx.x * blockDim.x + threadIdx.x;
    if (i >= N_NODES) return;
    g_rowptr[i] = g_tmp[i] - g_cnt[i] + g_boff[i >> 10];
    float x0 = x[i * 3 + 0], x1 = x[i * 3 + 1], x2 = x[i * 3 + 2];
    #pragma unroll
    for (int r = 0; r < 8; r++) {
        float v = x0 * g_P1[r] + x1 * g_P1[8 + r] + x2 * g_P1[16 + r];
        int h = r >> 1;
        if (r & 1) g_ed[i * 4 + h] = v;
        else       g_es[i * 4 + h] = v;
    }
}

__global__ void k_fill(const int* __restrict__ ei) {
    int i = blockIdx.x * blockDim.x + threadIdx.x;
    if (i < N_EDGES) {
        int s = ei[i];
        int d = ei[N_EDGES + i];
        int pos = g_rowptr[d] + atomicAdd(&g_fill[d], 1);
        g_colsrc[pos] = s;
    }
}

// ---------------- pack helpers ----------------
__device__ __forceinline__ unsigned pack_h2(float a, float b) {
    __half2 h = __floats2half2_rn(a, b);
    return *(unsigned*)&h;
}
__device__ __forceinline__ float2 unpack_h2(unsigned u) {
    return __half22float2(*(__half2*)&u);
}
__device__ __forceinline__ float lky(float v) {
    v = v > 0.f ? v : SLOPE * v;
    return fminf(fmaxf(v, -60.f), 60.f);
}

// ---------------- layer-1 edge loop ONLY (R12 pattern, warp per node) ----------------
// Writes normalized per-head raw-feature aggregate A1[n][h*3+k] (12 floats).
__global__ void __launch_bounds__(256) k_l1a(const float* __restrict__ x) {
    int warp = (blockIdx.x * blockDim.x + threadIdx.x) >> 5;
    if (warp >= N_NODES) return;
    int lane = threadIdx.x & 31;
    int n = warp;
    int h = lane >> 3, kp = lane & 7;
    float my_ed = g_ed[n * 4 + h];
    int beg = g_rowptr[n], end = g_rowptr[n + 1];

    float acc = 0.f, ssum = 0.f;
    int e = beg;
    for (; e + 4 <= end; e += 4) {
        int t0 = g_colsrc[e + 0];
        int t1 = g_colsrc[e + 1];
        int t2 = g_colsrc[e + 2];
        int t3 = g_colsrc[e + 3];
        float l0 = g_es[t0 * 4 + h];
        float l1 = g_es[t1 * 4 + h];
        float l2 = g_es[t2 * 4 + h];
        float l3 = g_es[t3 * 4 + h];
        float xa = (kp < 3) ? x[t0 * 3 + kp] : 0.f;
        float xb = (kp < 3) ? x[t1 * 3 + kp] : 0.f;
        float xc = (kp < 3) ? x[t2 * 3 + kp] : 0.f;
        float xd = (kp < 3) ? x[t3 * 3 + kp] : 0.f;
        float w0 = __expf(lky(l0 + my_ed));
        float w1 = __expf(lky(l1 + my_ed));
        float w2 = __expf(lky(l2 + my_ed));
        float w3 = __expf(lky(l3 + my_ed));
        ssum += (w0 + w1) + (w2 + w3);
        acc += (w0 * xa + w1 * xb) + (w2 * xc + w3 * xd);
    }
    for (; e < end; e++) {
        int t0 = g_colsrc[e];
        float w0 = __expf(lky(g_es[t0 * 4 + h] + my_ed));
        float xa = (kp < 3) ? x[t0 * 3 + kp] : 0.f;
        ssum += w0;
        acc += w0 * xa;
    }
    float inv = (end > beg) ? 1.f / ssum : 0.f;
    if (kp < 3) g_A1[(size_t)n * 12 + h * 3 + kp] = acc * inv;
}

// ---------------- layer-1 transform (node per thread): h1 + es2/ed2 ----------------
__global__ void __launch_bounds__(256) k_l1b(const float* __restrict__ W1,
                                             const float* __restrict__ b1) {
    __shared__ float w1s[768];
    __shared__ float p2s[512];
    __shared__ float b1s[64];
    for (int i = threadIdx.x; i < 768; i += 256) w1s[i] = W1[i];
    for (int i = threadIdx.x; i < 512; i += 256) p2s[i] = g_P2[i];
    if (threadIdx.x < 64) b1s[threadIdx.x] = b1[threadIdx.x];
    __syncthreads();
    int n = blockIdx.x * blockDim.x + threadIdx.x;
    if (n >= N_NODES) return;

    float A[12];
    #pragma unroll
    for (int i = 0; i < 12; i++) A[i] = g_A1[(size_t)n * 12 + i];
    #pragma unroll
    for (int i = 0; i < 12; i++) A[i] *= 0.25f;   // fold head-mean

    float ar[8] = {0, 0, 0, 0, 0, 0, 0, 0};
    #pragma unroll
    for (int c0 = 0; c0 < 64; c0 += 8) {
        uint4 pack;
        unsigned* pu = (unsigned*)&pack;
        #pragma unroll
        for (int j = 0; j < 8; j += 2) {
            int c = c0 + j;
            float v0 = b1s[c], v1 = b1s[c + 1];
            #pragma unroll
            for (int hh = 0; hh < 4; hh++)
                #pragma unroll
                for (int k = 0; k < 3; k++) {
                    float2 wv = *(const float2*)&w1s[k * 256 + hh * 64 + c];
                    float a = A[hh * 3 + k];
                    v0 += a * wv.x;
                    v1 += a * wv.y;
                }
            v0 = fmaxf(v0, 0.f);
            v1 = fmaxf(v1, 0.f);
            float4 p0a = *(const float4*)&p2s[c * 8];
            float4 p0b = *(const float4*)&p2s[c * 8 + 4];
            float4 p1a = *(const float4*)&p2s[(c + 1) * 8];
            float4 p1b = *(const float4*)&p2s[(c + 1) * 8 + 4];
            ar[0] += v0 * p0a.x + v1 * p1a.x;
            ar[1] += v0 * p0a.y + v1 * p1a.y;
            ar[2] += v0 * p0a.z + v1 * p1a.z;
            ar[3] += v0 * p0a.w + v1 * p1a.w;
            ar[4] += v0 * p0b.x + v1 * p1b.x;
            ar[5] += v0 * p0b.y + v1 * p1b.y;
            ar[6] += v0 * p0b.z + v1 * p1b.z;
            ar[7] += v0 * p0b.w + v1 * p1b.w;
            pu[j >> 1] = pack_h2(v0, v1);
        }
        *(uint4*)(g_h1h + (size_t)n * 64 + c0) = pack;
    }
    #pragma unroll
    for (int hh = 0; hh < 4; hh++) {
        g_es2[n * 4 + hh] = ar[2 * hh];
        g_ed2[n * 4 + hh] = ar[2 * hh + 1];
    }
}

// ---------------- layer-2 aggregation (warp per node), 4-edge unroll [R12] ----------------
__global__ void __launch_bounds__(256) k_agg2() {
    int warp = (blockIdx.x * blockDim.x + threadIdx.x) >> 5;
    if (warp >= N_NODES) return;
    int lane = threadIdx.x & 31;
    int n = warp;
    int h = lane >> 3, kp = lane & 7;
    float my_ed = g_ed2[n * 4 + h];
    int beg = g_rowptr[n], end = g_rowptr[n + 1];

    const uint4* h14 = (const uint4*)g_h1h;   // node row = 8 uint4 (128 B)
    float acc[8] = {0, 0, 0, 0, 0, 0, 0, 0};
    float ssum = 0.f;
    int e = beg;
    for (; e + 4 <= end; e += 4) {
        int t0 = g_colsrc[e + 0];
        int t1 = g_colsrc[e + 1];
        int t2 = g_colsrc[e + 2];
        int t3 = g_colsrc[e + 3];
        float l0 = g_es2[t0 * 4 + h];
        float l1 = g_es2[t1 * 4 + h];
        float l2 = g_es2[t2 * 4 + h];
        float l3 = g_es2[t3 * 4 + h];
        uint4 r0 = h14[(size_t)t0 * 8 + kp];
        uint4 r1 = h14[(size_t)t1 * 8 + kp];
        uint4 r2 = h14[(size_t)t2 * 8 + kp];
        uint4 r3 = h14[(size_t)t3 * 8 + kp];
        float w0 = __expf(lky(l0 + my_ed));
        float w1 = __expf(lky(l1 + my_ed));
        float w2 = __expf(lky(l2 + my_ed));
        float w3 = __expf(lky(l3 + my_ed));
        ssum += (w0 + w1) + (w2 + w3);
        float2 f;
        f = unpack_h2(r0.x); acc[0] += w0 * f.x; acc[1] += w0 * f.y;
        f = unpack_h2(r0.y); acc[2] += w0 * f.x; acc[3] += w0 * f.y;
        f = unpack_h2(r0.z); acc[4] += w0 * f.x; acc[5] += w0 * f.y;
        f = unpack_h2(r0.w); acc[6] += w0 * f.x; acc[7] += w0 * f.y;
        f = unpack_h2(r1.x); acc[0] += w1 * f.x; acc[1] += w1 * f.y;
        f = unpack_h2(r1.y); acc[2] += w1 * f.x; acc[3] += w1 * f.y;
        f = unpack_h2(r1.z); acc[4] += w1 * f.x; acc[5] += w1 * f.y;
        f = unpack_h2(r1.w); acc[6] += w1 * f.x; acc[7] += w1 * f.y;
        f = unpack_h2(r2.x); acc[0] += w2 * f.x; acc[1] += w2 * f.y;
        f = unpack_h2(r2.y); acc[2] += w2 * f.x; acc[3] += w2 * f.y;
        f = unpack_h2(r2.z); acc[4] += w2 * f.x; acc[5] += w2 * f.y;
        f = unpack_h2(r2.w); acc[6] += w2 * f.x; acc[7] += w2 * f.y;
        f = unpack_h2(r3.x); acc[0] += w3 * f.x; acc[1] += w3 * f.y;
        f = unpack_h2(r3.y); acc[2] += w3 * f.x; acc[3] += w3 * f.y;
        f = unpack_h2(r3.z); acc[4] += w3 * f.x; acc[5] += w3 * f.y;
        f = unpack_h2(r3.w); acc[6] += w3 * f.x; acc[7] += w3 * f.y;
    }
    for (; e < end; e++) {
        int t0 = g_colsrc[e];
        float w0 = __expf(lky(g_es2[t0 * 4 + h] + my_ed));
        uint4 r0 = h14[(size_t)t0 * 8 + kp];
        ssum += w0;
        float2 f;
        f = unpack_h2(r0.x); acc[0] += w0 * f.x; acc[1] += w0 * f.y;
        f = unpack_h2(r0.y); acc[2] += w0 * f.x; acc[3] += w0 * f.y;
        f = unpack_h2(r0.z); acc[4] += w0 * f.x; acc[5] += w0 * f.y;
        f = unpack_h2(r0.w); acc[6] += w0 * f.x; acc[7] += w0 * f.y;
    }
    float inv = (end > beg) ? 1.f / ssum : 0.f;
    uint4 o;
    o.x = pack_h2(acc[0] * inv, acc[1] * inv);
    o.y = pack_h2(acc[2] * inv, acc[3] * inv);
    o.z = pack_h2(acc[4] * inv, acc[5] * inv);
    o.w = pack_h2(acc[6] * inv, acc[7] * inv);
    *(uint4*)(g_Ah + (size_t)n * 256 + lane * 8) = o;
}

// ---------------- output GEMM via HMMA + FUSED global-add-pool [R12] ----------------
__global__ void __launch_bounds__(256) k_out(const float* __restrict__ b2,
                                             const int* __restrict__ batch,
                                             float* __restrict__ out) {
    __shared__ __align__(16) char sbuf[32768];       // sA/sB aliased with sH
    __half* sA = (__half*)sbuf;                      // 128*72*2 = 18432 B
    __half* sB = (__half*)(sbuf + 18432);            // 64*72*2  =  9216 B
    float*  sH = (float*)sbuf;                       // 128*64*4 = 32768 B (reused)

    int n0 = blockIdx.x * 128;
    int tid = threadIdx.x, wid = tid >> 5, lane = tid & 31;
    int g = lane >> 2, tg = lane & 3;
    float acc[8][4];
    #pragma unroll
    for (int i = 0; i < 8; i++)
        #pragma unroll
        for (int j = 0; j < 4; j++) acc[i][j] = 0.f;

    for (int kc = 0; kc < 4; kc++) {
        int k0 = kc * 64;
        __syncthreads();
        #pragma unroll
        for (int i = 0; i < 4; i++) {
            int q = tid + i * 256;
            int r = q >> 3, u = q & 7;
            int node = n0 + r;
            uint4 v = make_uint4(0, 0, 0, 0);
            if (node < N_NODES) v = *(const uint4*)(g_Ah + (size_t)node * 256 + k0 + u * 8);
            *(uint4*)(sA + r * 72 + u * 8) = v;
        }
        #pragma unroll
        for (int i = 0; i < 2; i++) {
            int q = tid + i * 256;
            int c = q >> 3, u = q & 7;
            *(uint4*)(sB + c * 72 + u * 8) = *(const uint4*)(g_W2f + c * 256 + k0 + u * 8);
        }
        __syncthreads();
        #pragma unroll
        for (int ks = 0; ks < 4; ks++) {
            int k1 = ks * 16;
            int arow = wid * 16 + g;
            unsigned a0 = *(unsigned*)(sA + arow * 72 + k1 + tg * 2);
            unsigned a1 = *(unsigned*)(sA + (arow + 8) * 72 + k1 + tg * 2);
            unsigned a2 = *(unsigned*)(sA + arow * 72 + k1 + 8 + tg * 2);
            unsigned a3 = *(unsigned*)(sA + (arow + 8) * 72 + k1 + 8 + tg * 2);
            #pragma unroll
            for (int nt = 0; nt < 8; nt++) {
                unsigned b0 = *(unsigned*)(sB + (nt * 8 + g) * 72 + k1 + tg * 2);
                unsigned b1 = *(unsigned*)(sB + (nt * 8 + g) * 72 + k1 + 8 + tg * 2);
                asm volatile(
                    "mma.sync.aligned.m16n8k16.row.col.f32.f16.f16.f32 "
                    "{%0,%1,%2,%3}, {%4,%5,%6,%7}, {%8,%9}, {%0,%1,%2,%3};\n"
                    : "+f"(acc[nt][0]), "+f"(acc[nt][1]), "+f"(acc[nt][2]), "+f"(acc[nt][3])
                    : "r"(a0), "r"(a1), "r"(a2), "r"(a3), "r"(b0), "r"(b1));
            }
        }
    }
    __syncthreads();   // done with sA/sB; sH takes over the buffer

    int row0 = wid * 16 + g;
    #pragma unroll
    for (int nt = 0; nt < 8; nt++) {
        int c = nt * 8 + tg * 2;
        float bb0 = b2[c], bb1 = b2[c + 1];
        sH[row0 * 64 + c]       = fmaxf(acc[nt][0] + bb0, 0.f);
        sH[row0 * 64 + c + 1]   = fmaxf(acc[nt][1] + bb1, 0.f);
        sH[(row0 + 8) * 64 + c]     = fmaxf(acc[nt][2] + bb0, 0.f);
        sH[(row0 + 8) * 64 + c + 1] = fmaxf(acc[nt][3] + bb1, 0.f);
    }
    __syncthreads();

    // pooled reduction: 4 threads per channel, each scans 32 rows
    int c = tid & 63;
    int part = tid >> 6;
    int r0 = part * 32;
    float pacc = 0.f;
    int cur = -1;
    #pragma unroll 4
    for (int r = r0; r < r0 + 32; r++) {
        int node = n0 + r;
        if (node >= N_NODES) break;
        int gg = batch[node];
        if (gg != cur) {
            if (cur >= 0) atomicAdd(&out[cur * 64 + c], pacc);
            cur = gg;
            pacc = 0.f;
        }
        pacc += sH[r * 64 + c];
    }
    if (cur >= 0) atomicAdd(&out[cur * 64 + c], pacc);
}

// ---------------- launch ----------------
extern "C" void kernel_launch(void* const* d_in, const int* in_sizes, int n_in,
                              void* d_out, int out_size) {
    const float* x     = (const float*)d_in[0];
    const int*   ei    = (const int*)d_in[1];
    const int*   batch = (const int*)d_in[2];
    const float* W1 = (const float*)d_in[3];
    const float* a_src1 = (const float*)d_in[4];
    const float* a_dst1 = (const float*)d_in[5];
    const float* b1 = (const float*)d_in[6];
    const float* W2 = (const float*)d_in[7];
    const float* a_src2 = (const float*)d_in[8];
    const float* a_dst2 = (const float*)d_in[9];
    const float* b2 = (const float*)d_in[10];
    float* out = (float*)d_out;

    const int NB_N  = (N_NODES + 255) / 256;
    const int NB_E  = (N_EDGES + 255) / 256;
    const int NB_W  = (N_NODES * 32 + 255) / 256;
    const int NB_S1 = (N_NODES + 1023) / 1024;
    const int NB_O  = (N_NODES + 127) / 128;

    k_zero<<<NB_N, 256>>>(out);
    k_count<<<NB_E, 256>>>(ei);
    k_prep<<<33, 512>>>(W1, a_src1, a_dst1, W2, a_src2, a_dst2);
    k_scan1<<<NB_S1, 1024>>>();
    k_scan3x<<<NB_N, 256>>>(x);
    k_fill<<<NB_E, 256>>>(ei);

    k_l1a<<<NB_W, 256>>>(x);             // edge gather -> A1 (12 floats/node)
    k_l1b<<<NB_N, 256>>>(W1, b1);        // node transform: h1 + es2/ed2
    k_agg2<<<NB_W, 256>>>();
    k_out<<<NB_O, 256>>>(b2, batch, out);
}